// round 15
// baseline (speedup 1.0000x reference)
#include <cuda_runtime.h>
#include <cuda_fp16.h>
#include <math.h>

#define BB   2048
#define IND  784
#define HH   512
#define OUTD 512
#define NE   8
#define NER  4
#define TT   28
#define G4H  2048
#define NSLAB 17

// ---------------- device scratch (no allocation) ----------------
__device__ __half g_Wblk[(size_t)NER * 16 * NSLAB * 128 * 32];  // [e][nt][slab][128][32] swizzled
__device__ float  g_bcat[NER * G4H];
__device__ __half g_xpadC[(size_t)TT * NER * BB * 32];          // [t][e][row][32] compact+swizzled
__device__ __half g_hblk[2][(size_t)NER * 16 * BB * 32];        // [buf][e][kb][row][32] swizzled
__device__ float  g_hf[(size_t)NER * BB * HH];                  // plain h_last for fc
__device__ float  g_c[(size_t)NER * BB * HH];
__device__ float  g_w[BB * NE];
__device__ float  g_eo[(size_t)NE * BB * OUTD];
__device__ float  g_h1[(size_t)NER * BB * HH];
__device__ int    g_sel[NE * BB];
__device__ int    g_idx[NER * BB];
__device__ int    g_cnt[NER];

// ---------------- helpers ----------------
__device__ __forceinline__ unsigned tf32r(float x) {
    unsigned u; asm("cvt.rna.tf32.f32 %0, %1;" : "=r"(u) : "f"(x)); return u;
}
__device__ __forceinline__ float fsig(float x) {
    float e; asm("ex2.approx.f32 %0, %1;" : "=f"(e) : "f"(-1.4426950408889634f * x));
    float r; asm("rcp.approx.f32 %0, %1;" : "=f"(r) : "f"(1.0f + e));
    return r;
}
__device__ __forceinline__ float ftanh_(float x) { return fmaf(2.0f, fsig(2.0f * x), -1.0f); }
__device__ __forceinline__ void ldsm4(unsigned& r0, unsigned& r1, unsigned& r2, unsigned& r3,
                                      unsigned addr) {
    asm volatile("ldmatrix.sync.aligned.m8n8.x4.shared.b16 {%0,%1,%2,%3}, [%4];"
                 : "=r"(r0), "=r"(r1), "=r"(r2), "=r"(r3) : "r"(addr));
}
__device__ __forceinline__ void bulk_g2s(unsigned dst, const void* src, unsigned bytes,
                                         unsigned mbar) {
    asm volatile(
        "cp.async.bulk.shared::cluster.global.mbarrier::complete_tx::bytes [%0], [%1], %2, [%3];"
        :: "r"(dst), "l"(src), "r"(bytes), "r"(mbar) : "memory");
}
__device__ __forceinline__ void mbar_init(unsigned mbar, unsigned count) {
    asm volatile("mbarrier.init.shared.b64 [%0], %1;" :: "r"(mbar), "r"(count) : "memory");
}
__device__ __forceinline__ void mbar_expect(unsigned mbar, unsigned bytes) {
    asm volatile("mbarrier.arrive.expect_tx.shared.b64 _, [%0], %1;"
                 :: "r"(mbar), "r"(bytes) : "memory");
}
__device__ __forceinline__ void mbar_wait(unsigned mbar, unsigned parity) {
    asm volatile(
        "{\n\t.reg .pred P1;\n\t"
        "WL_%=:\n\t"
        "mbarrier.try_wait.parity.acquire.cta.shared::cta.b64 P1, [%0], %1, 0x989680;\n\t"
        "@P1 bra.uni WD_%=;\n\t"
        "bra.uni WL_%=;\n\t"
        "WD_%=:\n\t}"
        :: "r"(mbar), "r"(parity) : "memory");
}
__device__ __forceinline__ void gdc_wait() {
    asm volatile("griddepcontrol.wait;" ::: "memory");
}
__device__ __forceinline__ void gdc_launch() {
    asm volatile("membar.gl;" ::: "memory");
    asm volatile("griddepcontrol.launch_dependents;" ::: "memory");
}

// ---------------- gate: softmax / top-5 / renorm (fp32 exact) + selection mask ----------------
__global__ void gate_kernel(const float* __restrict__ x, const float* __restrict__ Wg,
                            const float* __restrict__ bg, float* __restrict__ w)
{
    int b = blockIdx.x;
    int lane = threadIdx.x & 31, wid = threadIdx.x >> 5;
    __shared__ float sc[NE];
    const float* xr = x + (long)b * IND;
    const float* wr = Wg + (long)wid * IND;
    float s = 0.f;
    for (int i = lane; i < IND; i += 32) s += xr[i] * wr[i];
#pragma unroll
    for (int o = 16; o; o >>= 1) s += __shfl_xor_sync(0xffffffffu, s, o);
    if (lane == 0) sc[wid] = s + bg[wid];
    __syncthreads();
    if (threadIdx.x == 0) {
        float p[NE], mx = -1e30f;
#pragma unroll
        for (int e = 0; e < NE; e++) { p[e] = sc[e] * (1.0f / 2.718281828459045f); mx = fmaxf(mx, p[e]); }
        float sum = 0.f;
#pragma unroll
        for (int e = 0; e < NE; e++) { p[e] = expf(p[e] - mx); sum += p[e]; }
#pragma unroll
        for (int e = 0; e < NE; e++) p[e] /= sum;
        float ws = 0.f, wv[NE];
        int selv[NE];
#pragma unroll
        for (int e = 0; e < NE; e++) {
            int rank = 0;
#pragma unroll
            for (int j = 0; j < NE; j++)
                if (p[j] > p[e] || (p[j] == p[e] && j < e)) rank++;
            selv[e] = (rank < 5) ? 1 : 0;
            wv[e] = selv[e] ? p[e] : 0.f;
            ws += wv[e];
        }
        float inv = 1.0f / (ws + 1e-8f);
#pragma unroll
        for (int e = 0; e < NE; e++) {
            w[b * NE + e] = wv[e] * inv;
            g_sel[e * BB + b] = selv[e];
        }
    }
}

// ---------------- prep: blocked+swizzled W, bcat, c-init + compaction ----------------
__global__ void prep_compact(const float* __restrict__ Whh, const float* __restrict__ Wih,
                             const float* __restrict__ bih, const float* __restrict__ bhh)
{
    int nPrep = gridDim.x - NER;
    if ((int)blockIdx.x < nPrep) {
        long i = (long)blockIdx.x * 256 + threadIdx.x;
        if (i < (long)NER * G4H * 544) {
            int k = (int)(i % 544);
            int n = (int)((i / 544) & (G4H - 1));
            int e = (int)(i / (544L * G4H));
            int u = n >> 2, g = n & 3;
            int orow = g * 512 + u;
            float v = 0.0f;
            if (k < 512)      v = Whh[((long)e * G4H + orow) * HH + k];
            else if (k < 540) v = Wih[((long)e * G4H + orow) * 28 + (k - 512)];
            int nt = n >> 7, rl = n & 127, sb = k >> 5, kl = k & 31;
            int swz = (kl >> 3) ^ ((rl >> 1) & 3);
            size_t di = (((size_t)(e * 16 + nt) * NSLAB + sb) * 128 + rl) * 32 + swz * 8 + (kl & 7);
            g_Wblk[di] = __float2half_rn(v);
        }
        if (i < NER * G4H) {
            int row = (int)(i & (G4H - 1)), e = (int)(i >> 11);
            int u = row >> 2, g = row & 3;
            int orow = g * 512 + u;
            g_bcat[i] = bih[e * G4H + orow] + bhh[e * G4H + orow];
        }
        if (i < (long)NER * BB * HH) g_c[i] = 0.0f;
    } else {
        int e = (int)blockIdx.x - nPrep;
        int tid = threadIdx.x;                 // 256
        __shared__ int csum[256];
        int loc[8], s = 0;
#pragma unroll
        for (int j = 0; j < 8; j++) { loc[j] = g_sel[e * BB + tid * 8 + j]; s += loc[j]; }
        csum[tid] = s;
        __syncthreads();
        for (int off = 1; off < 256; off <<= 1) {
            int v = (tid >= off) ? csum[tid - off] : 0;
            __syncthreads();
            csum[tid] += v;
            __syncthreads();
        }
        int cnt = csum[255];
        int pos = csum[tid] - s;
#pragma unroll
        for (int j = 0; j < 8; j++)
            if (loc[j]) { g_idx[e * BB + pos] = tid * 8 + j; pos++; }
        for (int k = cnt + tid; k < BB; k += 256) g_idx[e * BB + k] = 0;
        if (tid == 0) g_cnt[e] = cnt;
    }
}

// ---------------- prep: gather x into compact order, blocked+swizzled ----------------
__global__ void prep_xc(const float* __restrict__ x) {
    long i = (long)blockIdx.x * 256 + threadIdx.x;   // TT*NER*BB*32
    if (i >= (long)TT * NER * BB * 32) return;
    int j = (int)(i & 31);
    int r = (int)((i >> 5) & (BB - 1));
    long rest = i >> 16;
    int e = (int)(rest & 3);
    int t = (int)(rest >> 2);
    int b = g_idx[e * BB + r];
    float v = (j < 28) ? x[(long)b * IND + t * 28 + j] : 0.0f;
    int swz = (j >> 3) ^ ((r >> 1) & 3);
    size_t di = (((size_t)t * NER + e) * BB + r) * 32 + swz * 8 + (j & 7);
    g_xpadC[di] = __float2half_rn(v);
}

// ---------------- fused recurrent GEMM (fp16, paired pipeline + PDL) + LSTM cell ----------------
// smem: mbar full[2] (count 2: B-phase arrive + A-phase arrive); pair-stages at +1024 (2 x 32768B).
__global__ __launch_bounds__(256, 2) void lstm_gemm(
    const __half* __restrict__ hIn, __half* __restrict__ hOut,
    float* __restrict__ hOutF, const __half* __restrict__ xpT, int sb0)
{
    extern __shared__ char smc[];
    unsigned mb = (unsigned)__cvta_generic_to_shared(smc);
    unsigned stgB = mb + 1024u;
    int e = blockIdx.z;
    int cnt = g_cnt[e];
    int tiles = (cnt + 127) >> 7;
    if ((int)blockIdx.y >= tiles) return;   // implicit trigger on exit
    int m0 = blockIdx.y * 128, n0 = blockIdx.x * 128;
    int nt = blockIdx.x;
    int tid = threadIdx.x, lane = tid & 31, wid = tid >> 5;
    int wm = wid >> 1, wn = wid & 1;
    const __half* Bw = g_Wblk + (size_t)(e * 16 + nt) * NSLAB * 4096;
    const __half* Ah = hIn + (size_t)e * 16 * BB * 32;
    const __half* Ax = xpT + (size_t)e * BB * 32;

    if (tid == 0) { mbar_init(mb, 2u); mbar_init(mb + 8u, 2u); }
    __syncthreads();

    int NSl = NSLAB - sb0;
    int NP = (NSl + 1) >> 1;

#define N2(p_)  ((2 * (p_) + 1 < NSl) ? 2 : 1)
#define ISSUE_B(p_) do {                                                        \
        int n2_ = N2(p_);                                                       \
        unsigned st_ = stgB + (unsigned)(((p_) & 1) * 32768);                   \
        unsigned mbar_ = mb + 8u * (unsigned)((p_) & 1);                        \
        mbar_expect(mbar_, 8192u * (unsigned)n2_);                              \
        for (int j_ = 0; j_ < n2_; j_++) {                                      \
            int sb_ = sb0 + 2 * (p_) + j_;                                      \
            bulk_g2s(st_ + (unsigned)j_ * 16384u + 8192u,                       \
                     Bw + (size_t)sb_ * 4096, 8192u, mbar_);                    \
        }                                                                       \
    } while (0)
#define ISSUE_A(p_) do {                                                        \
        int n2_ = N2(p_);                                                       \
        unsigned st_ = stgB + (unsigned)(((p_) & 1) * 32768);                   \
        unsigned mbar_ = mb + 8u * (unsigned)((p_) & 1);                        \
        mbar_expect(mbar_, 8192u * (unsigned)n2_);                              \
        for (int j_ = 0; j_ < n2_; j_++) {                                      \
            int sb_ = sb0 + 2 * (p_) + j_;                                      \
            const __half* as_ = (sb_ < 16)                                      \
                ? (Ah + ((size_t)sb_ * BB + m0) * 32)                           \
                : (Ax + (size_t)m0 * 32);                                       \
            bulk_g2s(st_ + (unsigned)j_ * 16384u, as_, 8192u, mbar_);           \
        }                                                                       \
    } while (0)

    // Pre-dependency: weight prefetch (step-independent data only)
    if (tid == 0) {
        ISSUE_B(0);
        if (NP > 1) ISSUE_B(1);
    }
    // Wait for predecessor step's h/c/x stores to be published
    gdc_wait();
    if (tid == 0) {
        ISSUE_A(0);
        if (NP > 1) ISSUE_A(1);
    }

    float acc[2][8][4] = {};
    int lm_mat = lane >> 3, lm_row = lane & 7;
    unsigned f_ = (unsigned)((lm_row >> 1) & 3);
    unsigned rA = (unsigned)(wm * 32 + (lm_mat & 1) * 8 + lm_row);
    unsigned cA = (unsigned)(lm_mat >> 1);

    for (int p = 0; p < NP; p++) {
        mbar_wait(mb + 8u * (unsigned)(p & 1), (unsigned)((p >> 1) & 1));
        int n2 = N2(p);
        for (int j = 0; j < n2; j++) {
            unsigned aSt = stgB + (unsigned)((p & 1) * 32768) + (unsigned)(j * 16384);
            unsigned bSt = aSt + 8192u;
#pragma unroll
            for (int ks = 0; ks < 2; ks++) {
                unsigned af[2][4], bf[8][2];
#pragma unroll
                for (int mt = 0; mt < 2; mt++) {
                    unsigned row = rA + (unsigned)(mt * 16);
                    unsigned addr = aSt + row * 64u + ((((unsigned)(2 * ks) + cA) ^ f_) << 4);
                    ldsm4(af[mt][0], af[mt][1], af[mt][2], af[mt][3], addr);
                }
#pragma unroll
                for (int q = 0; q < 2; q++)
#pragma unroll
                    for (int kh = 0; kh < 2; kh++) {
                        unsigned n = (unsigned)(wn * 64 + (q * 4 + lm_mat) * 8 + lm_row);
                        unsigned addr = bSt + n * 64u + ((((unsigned)(2 * ks + kh)) ^ f_) << 4);
                        ldsm4(bf[q * 4 + 0][kh], bf[q * 4 + 1][kh],
                              bf[q * 4 + 2][kh], bf[q * 4 + 3][kh], addr);
                    }
#pragma unroll
                for (int mt = 0; mt < 2; mt++)
#pragma unroll
                    for (int nt2 = 0; nt2 < 8; nt2++) {
                        asm volatile(
                            "mma.sync.aligned.m16n8k16.row.col.f32.f16.f16.f32 "
                            "{%0,%1,%2,%3}, {%4,%5,%6,%7}, {%8,%9}, {%0,%1,%2,%3};\n"
                            : "+f"(acc[mt][nt2][0]), "+f"(acc[mt][nt2][1]),
                              "+f"(acc[mt][nt2][2]), "+f"(acc[mt][nt2][3])
                            : "r"(af[mt][0]), "r"(af[mt][1]), "r"(af[mt][2]), "r"(af[mt][3]),
                              "r"(bf[nt2][0]), "r"(bf[nt2][1]));
                    }
            }
        }
        __syncthreads();                 // all warps done with pair p -> its stage is free
        if (tid == 0 && p + 2 < NP) { ISSUE_B(p + 2); ISSUE_A(p + 2); }
    }

    // -------- epilogue: stage gates in smem (128x132 fl), coalesced cell update --------
    float* sG = (float*)(smc + 1024);              // 128*132*4 = 67584 B
#pragma unroll
    for (int mt = 0; mt < 2; mt++) {
        int rl = wm * 32 + mt * 16 + (lane >> 2);
        int cl = wn * 64 + (lane & 3) * 2;
#pragma unroll
        for (int nt2 = 0; nt2 < 8; nt2++) {
            *(float2*)&sG[rl * 132 + cl + nt2 * 8]       = make_float2(acc[mt][nt2][0], acc[mt][nt2][1]);
            *(float2*)&sG[(rl + 8) * 132 + cl + nt2 * 8] = make_float2(acc[mt][nt2][2], acc[mt][nt2][3]);
        }
    }
    __syncthreads();

    int g8 = tid & 7, r0 = tid >> 3;
    int ub = n0 >> 2;
    float* cP = g_c + (size_t)e * BB * HH;
    float* hFP = hOutF ? (hOutF + (size_t)e * BB * HH) : (float*)0;
    __half* hBlk = hOut + (size_t)(e * 16 + nt) * BB * 32;
    const float* bc = g_bcat + e * G4H + n0 + g8 * 16;
#pragma unroll
    for (int k = 0; k < 4; k++) {
        int rl = r0 + k * 32;
        int rg = m0 + rl;
        const float* gr = sG + rl * 132 + g8 * 16;
        size_t gofs = (size_t)rg * HH + ub + g8 * 4;
        float4 cold = *(const float4*)(cP + gofs);
        float co[4] = { cold.x, cold.y, cold.z, cold.w };
        float hn[4], cn[4];
#pragma unroll
        for (int j = 0; j < 4; j++) {
            float4 bb = *(const float4*)(bc + 4 * j);
            float gi = gr[4 * j + 0] + bb.x;
            float gf = gr[4 * j + 1] + bb.y;
            float gg = gr[4 * j + 2] + bb.z;
            float go = gr[4 * j + 3] + bb.w;
            float cv = fsig(gf) * co[j] + fsig(gi) * ftanh_(gg);
            cn[j] = cv;
            hn[j] = fsig(go) * ftanh_(cv);
        }
        *(float4*)(cP + gofs) = make_float4(cn[0], cn[1], cn[2], cn[3]);
        unsigned swz = (unsigned)((g8 >> 1) ^ ((rg >> 1) & 3));
        size_t hb = (size_t)rg * 32 + swz * 8 + (g8 & 1) * 4;
        __half2 p0 = __floats2half2_rn(hn[0], hn[1]);
        __half2 p1 = __floats2half2_rn(hn[2], hn[3]);
        *(uint2*)(hBlk + hb) = make_uint2(*(unsigned*)&p0, *(unsigned*)&p1);
        if (hFP) *(float4*)(hFP + gofs) = make_float4(hn[0], hn[1], hn[2], hn[3]);
    }
    // publish stores, then allow the next step's grid to launch
    gdc_launch();
#undef ISSUE_A
#undef ISSUE_B
#undef N2
}

// ---------------- generic tf32 GEMM: C = A @ B^T (+bias)(+relu) ----------------
template<int EPI>  // 1 +bias, 2 +bias+relu
__global__ __launch_bounds__(256, 2) void gemm_tf32(
    const float* __restrict__ A, int lda, long aStr,
    const float* __restrict__ B, int ldb, long bStr,
    float* __restrict__ C, int ldc, long cStr,
    const float* __restrict__ bias, long biasStr, int K)
{
    __shared__ float As[128 * 32], Bs[128 * 32];
    int z = blockIdx.z;
    A += (long)z * aStr; B += (long)z * bStr; C += (long)z * cStr;
    int m0 = blockIdx.y * 128, n0 = blockIdx.x * 128;
    int tid = threadIdx.x, lane = tid & 31, wid = tid >> 5;
    int wm = wid >> 1, wn = wid & 1;
    float acc[2][8][4] = {};

    for (int kb = 0; kb < K; kb += 32) {
#pragma unroll
        for (int i = 0; i < 4; i++) {
            int f = tid + i * 256;
            int r = f >> 3, c4 = (f & 7) * 4;
            int k = kb + c4;
            int sc = c4 ^ ((r & 7) << 2);
            float4 v;
            const float* p = A + (long)(m0 + r) * lda + k;
            if (k + 4 <= K) v = *(const float4*)p;
            else { v.x = k < K ? p[0] : 0.f; v.y = k + 1 < K ? p[1] : 0.f;
                   v.z = k + 2 < K ? p[2] : 0.f; v.w = k + 3 < K ? p[3] : 0.f; }
            *(float4*)&As[r * 32 + sc] = v;
            const float* q = B + (long)(n0 + r) * ldb + k;
            if (k + 4 <= K) v = *(const float4*)q;
            else { v.x = k < K ? q[0] : 0.f; v.y = k + 1 < K ? q[1] : 0.f;
                   v.z = k + 2 < K ? q[2] : 0.f; v.w = k + 3 < K ? q[3] : 0.f; }
            *(float4*)&Bs[r * 32 + sc] = v;
        }
        __syncthreads();
#pragma unroll
        for (int ks = 0; ks < 4; ks++) {
            int k0 = ks * 8;
            unsigned af[2][4], bf[8][2];
#pragma unroll
            for (int mt = 0; mt < 2; mt++) {
                int r = wm * 32 + mt * 16 + (lane >> 2);
                int c = k0 + (lane & 3);
                int sw = (r & 7) << 2;
                int r8 = r + 8, sw8 = (r8 & 7) << 2;
                af[mt][0] = tf32r(As[r  * 32 + (c ^ sw)]);
                af[mt][1] = tf32r(As[r8 * 32 + (c ^ sw8)]);
                af[mt][2] = tf32r(As[r  * 32 + ((c + 4) ^ sw)]);
                af[mt][3] = tf32r(As[r8 * 32 + ((c + 4) ^ sw8)]);
            }
#pragma unroll
            for (int nt = 0; nt < 8; nt++) {
                int rn = wn * 64 + nt * 8 + (lane >> 2);
                int ck = k0 + (lane & 3);
                int sw = (rn & 7) << 2;
                bf[nt][0] = tf32r(Bs[rn * 32 + (ck ^ sw)]);
                bf[nt][1] = tf32r(Bs[rn * 32 + ((ck + 4) ^ sw)]);
            }
#pragma unroll
            for (int mt = 0; mt < 2; mt++)
#pragma unroll
                for (int nt = 0; nt < 8; nt++) {
                    asm volatile(
                        "mma.sync.aligned.m16n8k8.row.col.f32.tf32.tf32.f32 "
                        "{%0,%1,%2,%3}, {%4,%5,%6,%7}, {%8,%9}, {%0,%1,%2,%3};\n"
                        : "+f"(acc[mt][nt][0]), "+f"(acc[mt][nt][1]),
                          "+f"(acc[mt][nt][2]), "+f"(acc[mt][nt][3])
                        : "r"(af[mt][0]), "r"(af[mt][1]), "r"(af[mt][2]), "r"(af[mt][3]),
                          "r"(bf[nt][0]), "r"(bf[nt][1]));
                }
        }
        __syncthreads();
    }
#pragma unroll
    for (int mt = 0; mt < 2; mt++) {
        int r = m0 + wm * 32 + mt * 16 + (lane >> 2);
#pragma unroll
        for (int nt = 0; nt < 8; nt++) {
            int c = n0 + wn * 64 + nt * 8 + (lane & 3) * 2;
            const float* bp = bias + (long)z * biasStr;
            float b0 = bp[c], b1 = bp[c + 1];
            float v0 = acc[mt][nt][0] + b0, v1 = acc[mt][nt][1] + b1;
            float v2 = acc[mt][nt][2] + b0, v3 = acc[mt][nt][3] + b1;
            if (EPI == 2) {
                v0 = fmaxf(v0, 0.f); v1 = fmaxf(v1, 0.f);
                v2 = fmaxf(v2, 0.f); v3 = fmaxf(v3, 0.f);
            }
            *(float2*)&C[(long)r * ldc + c]       = make_float2(v0, v1);
            *(float2*)&C[(long)(r + 8) * ldc + c] = make_float2(v2, v3);
        }
    }
}

// ---------------- rec-expert fc GEMM, compact A, scatter epilogue ----------------
__global__ __launch_bounds__(256, 2) void fc_gemm_scatter(
    const float* __restrict__ A, const float* __restrict__ B,
    float* __restrict__ C, const float* __restrict__ bias)
{
    __shared__ float As[128 * 32], Bs[128 * 32];
    int z = blockIdx.z;
    int cnt = g_cnt[z];
    if ((int)blockIdx.y * 128 >= cnt) return;
    A += (long)z * BB * HH;
    B += (long)z * OUTD * HH;
    C += (long)z * BB * OUTD;
    int m0 = blockIdx.y * 128, n0 = blockIdx.x * 128;
    int tid = threadIdx.x, lane = tid & 31, wid = tid >> 5;
    int wm = wid >> 1, wn = wid & 1;
    float acc[2][8][4] = {};

    for (int kb = 0; kb < HH; kb += 32) {
#pragma unroll
        for (int i = 0; i < 4; i++) {
            int f = tid + i * 256;
            int r = f >> 3, c4 = (f & 7) * 4;
            int sc = c4 ^ ((r & 7) << 2);
            *(float4*)&As[r * 32 + sc] = *(const float4*)(A + (long)(m0 + r) * HH + kb + c4);
            *(float4*)&Bs[r * 32 + sc] = *(const float4*)(B + (long)(n0 + r) * HH + kb + c4);
        }
        __syncthreads();
#pragma unroll
        for (int ks = 0; ks < 4; ks++) {
            int k0 = ks * 8;
            unsigned af[2][4], bf[8][2];
#pragma unroll
            for (int mt = 0; mt < 2; mt++) {
                int r = wm * 32 + mt * 16 + (lane >> 2);
                int c = k0 + (lane & 3);
                int sw = (r & 7) << 2;
                int r8 = r + 8, sw8 = (r8 & 7) << 2;
                af[mt][0] = tf32r(As[r  * 32 + (c ^ sw)]);
                af[mt][1] = tf32r(As[r8 * 32 + (c ^ sw8)]);
                af[mt][2] = tf32r(As[r  * 32 + ((c + 4) ^ sw)]);
                af[mt][3] = tf32r(As[r8 * 32 + ((c + 4) ^ sw8)]);
            }
#pragma unroll
            for (int nt = 0; nt < 8; nt++) {
                int rn = wn * 64 + nt * 8 + (lane >> 2);
                int ck = k0 + (lane & 3);
                int sw = (rn & 7) << 2;
                bf[nt][0] = tf32r(Bs[rn * 32 + (ck ^ sw)]);
                bf[nt][1] = tf32r(Bs[rn * 32 + ((ck + 4) ^ sw)]);
            }
#pragma unroll
            for (int mt = 0; mt < 2; mt++)
#pragma unroll
                for (int nt = 0; nt < 8; nt++) {
                    asm volatile(
                        "mma.sync.aligned.m16n8k8.row.col.f32.tf32.tf32.f32 "
                        "{%0,%1,%2,%3}, {%4,%5,%6,%7}, {%8,%9}, {%0,%1,%2,%3};\n"
                        : "+f"(acc[mt][nt][0]), "+f"(acc[mt][nt][1]),
                          "+f"(acc[mt][nt][2]), "+f"(acc[mt][nt][3])
                        : "r"(af[mt][0]), "r"(af[mt][1]), "r"(af[mt][2]), "r"(af[mt][3]),
                          "r"(bf[nt][0]), "r"(bf[nt][1]));
                }
        }
        __syncthreads();
    }
#pragma unroll
    for (int mt = 0; mt < 2; mt++) {
        int r = m0 + wm * 32 + mt * 16 + (lane >> 2);
        int bi0 = (r < cnt)     ? g_idx[z * BB + r]     : -1;
        int bi1 = (r + 8 < cnt) ? g_idx[z * BB + r + 8] : -1;
#pragma unroll
        for (int nt = 0; nt < 8; nt++) {
            int c = n0 + wn * 64 + nt * 8 + (lane & 3) * 2;
            const float* bp = bias + (long)z * OUTD;
            float b0 = bp[c], b1 = bp[c + 1];
            if (bi0 >= 0)
                *(float2*)&C[(long)bi0 * OUTD + c] =
                    make_float2(acc[mt][nt][0] + b0, acc[mt][nt][1] + b1);
            if (bi1 >= 0)
                *(float2*)&C[(long)bi1 * OUTD + c] =
                    make_float2(acc[mt][nt][2] + b0, acc[mt][nt][3] + b1);
        }
    }
}

// ---------------- final combine ----------------
__global__ void combine_kernel(float* __restrict__ out) {
    int idx = blockIdx.x * blockDim.x + threadIdx.x;  // B*OUT
    int b = idx >> 9, o = idx & 511;
    float s = 0.f;
#pragma unroll
    for (int e = 0; e < NE; e++)
        s += g_w[b * NE + e] * g_eo[((long)e * BB + b) * OUTD + o];
    out[idx] = s;
}

// ---------------- launch ----------------
extern "C" void kernel_launch(void* const* d_in, const int* in_sizes, int n_in,
                              void* d_out, int out_size)
{
    const float* x    = (const float*)d_in[0];
    const float* Wg   = (const float*)d_in[1];
    const float* bg   = (const float*)d_in[2];
    const float* Wih  = (const float*)d_in[3];
    const float* Whh  = (const float*)d_in[4];
    const float* bih  = (const float*)d_in[5];
    const float* bhh  = (const float*)d_in[6];
    const float* fcW  = (const float*)d_in[7];
    const float* fcb  = (const float*)d_in[8];
    const float* W1   = (const float*)d_in[9];
    const float* b1   = (const float*)d_in[10];
    const float* W2   = (const float*)d_in[11];
    const float* b2   = (const float*)d_in[12];
    float* out = (float*)d_out;

    const int LG_SMEM = 1024 + 128 * 132 * 4;   // 68608 (>= 1024 + 2*32768 = 66560)
    cudaFuncSetAttribute(lstm_gemm, cudaFuncAttributeMaxDynamicSharedMemorySize, LG_SMEM);

    __half *xcP, *hb0;
    float *wp, *eop, *h1buf, *hfP;
    cudaGetSymbolAddress((void**)&xcP,   g_xpadC);
    cudaGetSymbolAddress((void**)&hb0,   g_hblk);
    cudaGetSymbolAddress((void**)&wp,    g_w);
    cudaGetSymbolAddress((void**)&eop,   g_eo);
    cudaGetSymbolAddress((void**)&h1buf, g_h1);
    cudaGetSymbolAddress((void**)&hfP,   g_hf);
    __half* hb1 = hb0 + (size_t)NER * 16 * BB * 32;
    __half* hbuf[2] = { hb0, hb1 };

    gate_kernel<<<BB, 256>>>(x, Wg, bg, wp);
    int nPrep = (int)(((long)NER * G4H * 544 + 255) / 256);
    prep_compact<<<nPrep + NER, 256>>>(Whh, Wih, bih, bhh);
    prep_xc<<<(int)(((long)TT * NER * BB * 32 + 255) / 256), 256>>>(x);

    // lstm chain with programmatic dependent launch
    cudaLaunchAttribute pdlAttr;
    pdlAttr.id = cudaLaunchAttributeProgrammaticStreamSerialization;
    pdlAttr.val.programmaticStreamSerializationAllowed = 1;
    for (int t = 0; t < TT; t++) {
        cudaLaunchConfig_t cfg = {};
        cfg.gridDim = dim3(16, 16, NER);
        cfg.blockDim = dim3(256, 1, 1);
        cfg.dynamicSmemBytes = LG_SMEM;
        cfg.stream = 0;
        cfg.attrs = &pdlAttr;
        cfg.numAttrs = 1;
        const __half* hIn = hbuf[t & 1];
        __half* hOut = hbuf[(t + 1) & 1];
        float* hOutF = (t == TT - 1) ? hfP : (float*)0;
        const __half* xpT = xcP + (size_t)t * NER * BB * 32;
        int sb0 = (t == 0) ? 16 : 0;
        cudaLaunchKernelEx(&cfg, lstm_gemm, hIn, hOut, hOutF, xpT, sb0);
    }

    fc_gemm_scatter<<<dim3(4, 16, NER), 256>>>(hfP, fcW, eop, fcb);

    gemm_tf32<2><<<dim3(4, 16, NER), 256>>>(
        x, IND, 0,
        W1, IND, (long)HH * IND,
        h1buf, HH, (long)BB * HH,
        b1, HH, IND);

    gemm_tf32<1><<<dim3(4, 16, NER), 256>>>(
        h1buf, HH, (long)BB * HH,
        W2, HH, (long)OUTD * HH,
        eop + (size_t)NER * BB * OUTD, OUTD, (long)BB * OUTD,
        b2, OUTD, HH);

    combine_kernel<<<(BB * OUTD) / 256, 256>>>(out);
}

// round 17
// speedup vs baseline: 1.0230x; 1.0230x over previous
#include <cuda_runtime.h>
#include <cuda_fp16.h>
#include <math.h>

#define BB   2048
#define IND  784
#define HH   512
#define OUTD 512
#define NE   8
#define NER  4
#define TT   28
#define G4H  2048
#define NSLAB 17

// ---------------- device scratch (no allocation) ----------------
__device__ __half g_Wblk[(size_t)NER * 16 * NSLAB * 128 * 32];  // [e][nt][slab][128][32] swizzled
__device__ float  g_bcat[NER * G4H];
__device__ __half g_xpadC[(size_t)TT * NER * BB * 32];          // [t][e][row][32] compact+swizzled
__device__ __half g_hblk[2][(size_t)NER * 16 * BB * 32];        // [buf][e][kb][row][32] swizzled
__device__ float  g_hf[(size_t)NER * BB * HH];                  // plain h_last for fc
__device__ float  g_c[(size_t)NER * BB * HH];
__device__ float  g_w[BB * NE];
__device__ float  g_eo[(size_t)NE * BB * OUTD];
__device__ float  g_h1[(size_t)NER * BB * HH];                  // compact h1 for simple experts
__device__ int    g_sel[NE * BB];
__device__ int    g_idx[NE * BB];                               // per-expert compact->batch index
__device__ int    g_cnt[NE];

// ---------------- helpers ----------------
__device__ __forceinline__ unsigned tf32r(float x) {
    unsigned u; asm("cvt.rna.tf32.f32 %0, %1;" : "=r"(u) : "f"(x)); return u;
}
__device__ __forceinline__ float fsig(float x) {
    float e; asm("ex2.approx.f32 %0, %1;" : "=f"(e) : "f"(-1.4426950408889634f * x));
    float r; asm("rcp.approx.f32 %0, %1;" : "=f"(r) : "f"(1.0f + e));
    return r;
}
__device__ __forceinline__ float ftanh_(float x) { return fmaf(2.0f, fsig(2.0f * x), -1.0f); }
__device__ __forceinline__ void ldsm4(unsigned& r0, unsigned& r1, unsigned& r2, unsigned& r3,
                                      unsigned addr) {
    asm volatile("ldmatrix.sync.aligned.m8n8.x4.shared.b16 {%0,%1,%2,%3}, [%4];"
                 : "=r"(r0), "=r"(r1), "=r"(r2), "=r"(r3) : "r"(addr));
}
__device__ __forceinline__ void bulk_g2s(unsigned dst, const void* src, unsigned bytes,
                                         unsigned mbar) {
    asm volatile(
        "cp.async.bulk.shared::cluster.global.mbarrier::complete_tx::bytes [%0], [%1], %2, [%3];"
        :: "r"(dst), "l"(src), "r"(bytes), "r"(mbar) : "memory");
}
__device__ __forceinline__ void mbar_init(unsigned mbar, unsigned count) {
    asm volatile("mbarrier.init.shared.b64 [%0], %1;" :: "r"(mbar), "r"(count) : "memory");
}
__device__ __forceinline__ void mbar_expect(unsigned mbar, unsigned bytes) {
    asm volatile("mbarrier.arrive.expect_tx.shared.b64 _, [%0], %1;"
                 :: "r"(mbar), "r"(bytes) : "memory");
}
__device__ __forceinline__ void mbar_wait(unsigned mbar, unsigned parity) {
    asm volatile(
        "{\n\t.reg .pred P1;\n\t"
        "WL_%=:\n\t"
        "mbarrier.try_wait.parity.acquire.cta.shared::cta.b64 P1, [%0], %1, 0x989680;\n\t"
        "@P1 bra.uni WD_%=;\n\t"
        "bra.uni WL_%=;\n\t"
        "WD_%=:\n\t}"
        :: "r"(mbar), "r"(parity) : "memory");
}

// ---------------- gate: softmax / top-5 / renorm (fp32 exact) + selection mask ----------------
__global__ void gate_kernel(const float* __restrict__ x, const float* __restrict__ Wg,
                            const float* __restrict__ bg, float* __restrict__ w)
{
    int b = blockIdx.x;
    int lane = threadIdx.x & 31, wid = threadIdx.x >> 5;
    __shared__ float sc[NE];
    const float* xr = x + (long)b * IND;
    const float* wr = Wg + (long)wid * IND;
    float s = 0.f;
    for (int i = lane; i < IND; i += 32) s += xr[i] * wr[i];
#pragma unroll
    for (int o = 16; o; o >>= 1) s += __shfl_xor_sync(0xffffffffu, s, o);
    if (lane == 0) sc[wid] = s + bg[wid];
    __syncthreads();
    if (threadIdx.x == 0) {
        float p[NE], mx = -1e30f;
#pragma unroll
        for (int e = 0; e < NE; e++) { p[e] = sc[e] * (1.0f / 2.718281828459045f); mx = fmaxf(mx, p[e]); }
        float sum = 0.f;
#pragma unroll
        for (int e = 0; e < NE; e++) { p[e] = expf(p[e] - mx); sum += p[e]; }
#pragma unroll
        for (int e = 0; e < NE; e++) p[e] /= sum;
        float ws = 0.f, wv[NE];
        int selv[NE];
#pragma unroll
        for (int e = 0; e < NE; e++) {
            int rank = 0;
#pragma unroll
            for (int j = 0; j < NE; j++)
                if (p[j] > p[e] || (p[j] == p[e] && j < e)) rank++;
            selv[e] = (rank < 5) ? 1 : 0;
            wv[e] = selv[e] ? p[e] : 0.f;
            ws += wv[e];
        }
        float inv = 1.0f / (ws + 1e-8f);
#pragma unroll
        for (int e = 0; e < NE; e++) {
            w[b * NE + e] = wv[e] * inv;
            g_sel[e * BB + b] = selv[e];
        }
    }
}

// ---------------- prep: blocked+swizzled W, bcat, c-init + compaction (ALL 8 experts) ----------------
__global__ void prep_compact(const float* __restrict__ Whh, const float* __restrict__ Wih,
                             const float* __restrict__ bih, const float* __restrict__ bhh)
{
    int nPrep = gridDim.x - NE;
    if ((int)blockIdx.x < nPrep) {
        long i = (long)blockIdx.x * 256 + threadIdx.x;
        if (i < (long)NER * G4H * 544) {
            int k = (int)(i % 544);
            int n = (int)((i / 544) & (G4H - 1));
            int e = (int)(i / (544L * G4H));
            int u = n >> 2, g = n & 3;
            int orow = g * 512 + u;
            float v = 0.0f;
            if (k < 512)      v = Whh[((long)e * G4H + orow) * HH + k];
            else if (k < 540) v = Wih[((long)e * G4H + orow) * 28 + (k - 512)];
            int nt = n >> 7, rl = n & 127, sb = k >> 5, kl = k & 31;
            int swz = (kl >> 3) ^ ((rl >> 1) & 3);
            size_t di = (((size_t)(e * 16 + nt) * NSLAB + sb) * 128 + rl) * 32 + swz * 8 + (kl & 7);
            g_Wblk[di] = __float2half_rn(v);
        }
        if (i < NER * G4H) {
            int row = (int)(i & (G4H - 1)), e = (int)(i >> 11);
            int u = row >> 2, g = row & 3;
            int orow = g * 512 + u;
            g_bcat[i] = bih[e * G4H + orow] + bhh[e * G4H + orow];
        }
        if (i < (long)NER * BB * HH) g_c[i] = 0.0f;
    } else {
        int e = (int)blockIdx.x - nPrep;      // 0..7
        int tid = threadIdx.x;                // 256
        __shared__ int csum[256];
        int loc[8], s = 0;
#pragma unroll
        for (int j = 0; j < 8; j++) { loc[j] = g_sel[e * BB + tid * 8 + j]; s += loc[j]; }
        csum[tid] = s;
        __syncthreads();
        for (int off = 1; off < 256; off <<= 1) {
            int v = (tid >= off) ? csum[tid - off] : 0;
            __syncthreads();
            csum[tid] += v;
            __syncthreads();
        }
        int cnt = csum[255];
        int pos = csum[tid] - s;
#pragma unroll
        for (int j = 0; j < 8; j++)
            if (loc[j]) { g_idx[e * BB + pos] = tid * 8 + j; pos++; }
        for (int k = cnt + tid; k < BB; k += 256) g_idx[e * BB + k] = 0;
        if (tid == 0) g_cnt[e] = cnt;
    }
}

// ---------------- prep: gather x into compact order, blocked+swizzled (rec experts) ----------------
__global__ void prep_xc(const float* __restrict__ x) {
    long i = (long)blockIdx.x * 256 + threadIdx.x;   // TT*NER*BB*32
    if (i >= (long)TT * NER * BB * 32) return;
    int j = (int)(i & 31);
    int r = (int)((i >> 5) & (BB - 1));
    long rest = i >> 16;
    int e = (int)(rest & 3);
    int t = (int)(rest >> 2);
    int b = g_idx[e * BB + r];
    float v = (j < 28) ? x[(long)b * IND + t * 28 + j] : 0.0f;
    int swz = (j >> 3) ^ ((r >> 1) & 3);
    size_t di = (((size_t)t * NER + e) * BB + r) * 32 + swz * 8 + (j & 7);
    g_xpadC[di] = __float2half_rn(v);
}

// ---------------- fused recurrent GEMM (fp16, paired bulk-copy pipeline) + LSTM cell ----------------
// smem: mbar full[2] at +0; pair-stages at +1024 (2 x 32768B, each = 2 slab slots of 16384B).
__global__ __launch_bounds__(256, 2) void lstm_gemm(
    const __half* __restrict__ hIn, __half* __restrict__ hOut,
    float* __restrict__ hOutF, const __half* __restrict__ xpT, int sb0)
{
    extern __shared__ char smc[];
    unsigned mb = (unsigned)__cvta_generic_to_shared(smc);
    unsigned stgB = mb + 1024u;
    int e = blockIdx.z;
    int cnt = g_cnt[e];
    int tiles = (cnt + 127) >> 7;
    if ((int)blockIdx.y >= tiles) return;
    int m0 = blockIdx.y * 128, n0 = blockIdx.x * 128;
    int nt = blockIdx.x;
    int tid = threadIdx.x, lane = tid & 31, wid = tid >> 5;
    int wm = wid >> 1, wn = wid & 1;
    const __half* Bw = g_Wblk + (size_t)(e * 16 + nt) * NSLAB * 4096;
    const __half* Ah = hIn + (size_t)e * 16 * BB * 32;
    const __half* Ax = xpT + (size_t)e * BB * 32;

    if (tid == 0) { mbar_init(mb, 1u); mbar_init(mb + 8u, 1u); }
    __syncthreads();

    int NSl = NSLAB - sb0;
    int NP = (NSl + 1) >> 1;

#define ISSUE_PAIR(p_) do {                                                     \
        int k0_ = 2 * (p_);                                                     \
        int n2_ = (k0_ + 1 < NSl) ? 2 : 1;                                      \
        unsigned st_ = stgB + (unsigned)(((p_) & 1) * 32768);                   \
        unsigned mbar_ = mb + 8u * (unsigned)((p_) & 1);                        \
        mbar_expect(mbar_, 16384u * (unsigned)n2_);                             \
        for (int j_ = 0; j_ < n2_; j_++) {                                      \
            int sb_ = sb0 + k0_ + j_;                                           \
            unsigned d_ = st_ + (unsigned)j_ * 16384u;                          \
            const __half* as_ = (sb_ < 16)                                      \
                ? (Ah + ((size_t)sb_ * BB + m0) * 32)                           \
                : (Ax + (size_t)m0 * 32);                                       \
            bulk_g2s(d_, as_, 8192u, mbar_);                                    \
            bulk_g2s(d_ + 8192u, Bw + (size_t)sb_ * 4096, 8192u, mbar_);        \
        }                                                                       \
    } while (0)

    if (tid == 0) {
        ISSUE_PAIR(0);
        if (NP > 1) ISSUE_PAIR(1);
    }

    float acc[2][8][4] = {};
    int lm_mat = lane >> 3, lm_row = lane & 7;
    unsigned f_ = (unsigned)((lm_row >> 1) & 3);
    unsigned rA = (unsigned)(wm * 32 + (lm_mat & 1) * 8 + lm_row);
    unsigned cA = (unsigned)(lm_mat >> 1);

    for (int p = 0; p < NP; p++) {
        mbar_wait(mb + 8u * (unsigned)(p & 1), (unsigned)((p >> 1) & 1));
        int n2 = (2 * p + 1 < NSl) ? 2 : 1;
        for (int j = 0; j < n2; j++) {
            unsigned aSt = stgB + (unsigned)((p & 1) * 32768) + (unsigned)(j * 16384);
            unsigned bSt = aSt + 8192u;
#pragma unroll
            for (int ks = 0; ks < 2; ks++) {
                unsigned af[2][4], bf[8][2];
#pragma unroll
                for (int mt = 0; mt < 2; mt++) {
                    unsigned row = rA + (unsigned)(mt * 16);
                    unsigned addr = aSt + row * 64u + ((((unsigned)(2 * ks) + cA) ^ f_) << 4);
                    ldsm4(af[mt][0], af[mt][1], af[mt][2], af[mt][3], addr);
                }
#pragma unroll
                for (int q = 0; q < 2; q++)
#pragma unroll
                    for (int kh = 0; kh < 2; kh++) {
                        unsigned n = (unsigned)(wn * 64 + (q * 4 + lm_mat) * 8 + lm_row);
                        unsigned addr = bSt + n * 64u + ((((unsigned)(2 * ks + kh)) ^ f_) << 4);
                        ldsm4(bf[q * 4 + 0][kh], bf[q * 4 + 1][kh],
                              bf[q * 4 + 2][kh], bf[q * 4 + 3][kh], addr);
                    }
#pragma unroll
                for (int mt = 0; mt < 2; mt++)
#pragma unroll
                    for (int nt2 = 0; nt2 < 8; nt2++) {
                        asm volatile(
                            "mma.sync.aligned.m16n8k16.row.col.f32.f16.f16.f32 "
                            "{%0,%1,%2,%3}, {%4,%5,%6,%7}, {%8,%9}, {%0,%1,%2,%3};\n"
                            : "+f"(acc[mt][nt2][0]), "+f"(acc[mt][nt2][1]),
                              "+f"(acc[mt][nt2][2]), "+f"(acc[mt][nt2][3])
                            : "r"(af[mt][0]), "r"(af[mt][1]), "r"(af[mt][2]), "r"(af[mt][3]),
                              "r"(bf[nt2][0]), "r"(bf[nt2][1]));
                    }
            }
        }
        __syncthreads();                 // all warps done with pair p -> its stage is free
        if (tid == 0 && p + 2 < NP) ISSUE_PAIR(p + 2);
    }

    // -------- epilogue: stage gates in smem (128x132 fl), coalesced cell update --------
    float* sG = (float*)(smc + 1024);              // 128*132*4 = 67584 B
#pragma unroll
    for (int mt = 0; mt < 2; mt++) {
        int rl = wm * 32 + mt * 16 + (lane >> 2);
        int cl = wn * 64 + (lane & 3) * 2;
#pragma unroll
        for (int nt2 = 0; nt2 < 8; nt2++) {
            *(float2*)&sG[rl * 132 + cl + nt2 * 8]       = make_float2(acc[mt][nt2][0], acc[mt][nt2][1]);
            *(float2*)&sG[(rl + 8) * 132 + cl + nt2 * 8] = make_float2(acc[mt][nt2][2], acc[mt][nt2][3]);
        }
    }
    __syncthreads();

    int g8 = tid & 7, r0 = tid >> 3;
    int ub = n0 >> 2;
    float* cP = g_c + (size_t)e * BB * HH;
    float* hFP = hOutF ? (hOutF + (size_t)e * BB * HH) : (float*)0;
    __half* hBlk = hOut + (size_t)(e * 16 + nt) * BB * 32;
    const float* bc = g_bcat + e * G4H + n0 + g8 * 16;
#pragma unroll
    for (int k = 0; k < 4; k++) {
        int rl = r0 + k * 32;
        int rg = m0 + rl;
        const float* gr = sG + rl * 132 + g8 * 16;
        size_t gofs = (size_t)rg * HH + ub + g8 * 4;
        float4 cold = *(const float4*)(cP + gofs);
        float co[4] = { cold.x, cold.y, cold.z, cold.w };
        float hn[4], cn[4];
#pragma unroll
        for (int j = 0; j < 4; j++) {
            float4 bb = *(const float4*)(bc + 4 * j);
            float gi = gr[4 * j + 0] + bb.x;
            float gf = gr[4 * j + 1] + bb.y;
            float gg = gr[4 * j + 2] + bb.z;
            float go = gr[4 * j + 3] + bb.w;
            float cv = fsig(gf) * co[j] + fsig(gi) * ftanh_(gg);
            cn[j] = cv;
            hn[j] = fsig(go) * ftanh_(cv);
        }
        *(float4*)(cP + gofs) = make_float4(cn[0], cn[1], cn[2], cn[3]);
        unsigned swz = (unsigned)((g8 >> 1) ^ ((rg >> 1) & 3));
        size_t hb = (size_t)rg * 32 + swz * 8 + (g8 & 1) * 4;
        __half2 p0 = __floats2half2_rn(hn[0], hn[1]);
        __half2 p1 = __floats2half2_rn(hn[2], hn[3]);
        *(uint2*)(hBlk + hb) = make_uint2(*(unsigned*)&p0, *(unsigned*)&p1);
        if (hFP) *(float4*)(hFP + gofs) = make_float4(hn[0], hn[1], hn[2], hn[3]);
    }
#undef ISSUE_PAIR
}

// ---------------- h1 = relu(x_gathered @ W1^T + b1), compact output ----------------
__global__ __launch_bounds__(256, 2) void h1_gemm_gather(
    const float* __restrict__ X, const float* __restrict__ W1f,
    float* __restrict__ H1, const float* __restrict__ b1)
{
    __shared__ float As[128 * 32], Bs[128 * 32];
    __shared__ int sIdx[128];
    int z = blockIdx.z;                    // 0..3 -> expert 4+z
    int cnt = g_cnt[4 + z];
    if ((int)blockIdx.y * 128 >= cnt) return;
    const float* B = W1f + (long)z * HH * IND;
    float* C = H1 + (long)z * BB * HH;
    int m0 = blockIdx.y * 128, n0 = blockIdx.x * 128;
    int tid = threadIdx.x, lane = tid & 31, wid = tid >> 5;
    int wm = wid >> 1, wn = wid & 1;
    if (tid < 128) sIdx[tid] = g_idx[(4 + z) * BB + m0 + tid];
    __syncthreads();
    float acc[2][8][4] = {};

    for (int kb = 0; kb < IND; kb += 32) {
#pragma unroll
        for (int i = 0; i < 4; i++) {
            int f = tid + i * 256;
            int r = f >> 3, c4 = (f & 7) * 4;
            int k = kb + c4;
            int sc = c4 ^ ((r & 7) << 2);
            float4 v = make_float4(0.f, 0.f, 0.f, 0.f);
            if (k < IND) v = *(const float4*)(X + (long)sIdx[r] * IND + k);
            *(float4*)&As[r * 32 + sc] = v;
            float4 w = make_float4(0.f, 0.f, 0.f, 0.f);
            if (k < IND) w = *(const float4*)(B + (long)(n0 + r) * IND + k);
            *(float4*)&Bs[r * 32 + sc] = w;
        }
        __syncthreads();
#pragma unroll
        for (int ks = 0; ks < 4; ks++) {
            int k0 = ks * 8;
            unsigned af[2][4], bf[8][2];
#pragma unroll
            for (int mt = 0; mt < 2; mt++) {
                int r = wm * 32 + mt * 16 + (lane >> 2);
                int c = k0 + (lane & 3);
                int sw = (r & 7) << 2;
                int r8 = r + 8, sw8 = (r8 & 7) << 2;
                af[mt][0] = tf32r(As[r  * 32 + (c ^ sw)]);
                af[mt][1] = tf32r(As[r8 * 32 + (c ^ sw8)]);
                af[mt][2] = tf32r(As[r  * 32 + ((c + 4) ^ sw)]);
                af[mt][3] = tf32r(As[r8 * 32 + ((c + 4) ^ sw8)]);
            }
#pragma unroll
            for (int nt = 0; nt < 8; nt++) {
                int rn = wn * 64 + nt * 8 + (lane >> 2);
                int ck = k0 + (lane & 3);
                int sw = (rn & 7) << 2;
                bf[nt][0] = tf32r(Bs[rn * 32 + (ck ^ sw)]);
                bf[nt][1] = tf32r(Bs[rn * 32 + ((ck + 4) ^ sw)]);
            }
#pragma unroll
            for (int mt = 0; mt < 2; mt++)
#pragma unroll
                for (int nt = 0; nt < 8; nt++) {
                    asm volatile(
                        "mma.sync.aligned.m16n8k8.row.col.f32.tf32.tf32.f32 "
                        "{%0,%1,%2,%3}, {%4,%5,%6,%7}, {%8,%9}, {%0,%1,%2,%3};\n"
                        : "+f"(acc[mt][nt][0]), "+f"(acc[mt][nt][1]),
                          "+f"(acc[mt][nt][2]), "+f"(acc[mt][nt][3])
                        : "r"(af[mt][0]), "r"(af[mt][1]), "r"(af[mt][2]), "r"(af[mt][3]),
                          "r"(bf[nt][0]), "r"(bf[nt][1]));
                }
        }
        __syncthreads();
    }
#pragma unroll
    for (int mt = 0; mt < 2; mt++) {
        int r = m0 + wm * 32 + mt * 16 + (lane >> 2);
#pragma unroll
        for (int nt = 0; nt < 8; nt++) {
            int c = n0 + wn * 64 + nt * 8 + (lane & 3) * 2;
            float b0 = b1[(long)z * HH + c], bb1 = b1[(long)z * HH + c + 1];
            float v0 = fmaxf(acc[mt][nt][0] + b0, 0.f), v1 = fmaxf(acc[mt][nt][1] + bb1, 0.f);
            float v2 = fmaxf(acc[mt][nt][2] + b0, 0.f), v3 = fmaxf(acc[mt][nt][3] + bb1, 0.f);
            *(float2*)&C[(long)r * HH + c]       = make_float2(v0, v1);
            *(float2*)&C[(long)(r + 8) * HH + c] = make_float2(v2, v3);
        }
    }
}

// ---------------- GEMM with compact A, scatter epilogue (fc + simp) ----------------
__global__ __launch_bounds__(256, 2) void fc_gemm_scatter(
    const float* __restrict__ A, const float* __restrict__ B,
    float* __restrict__ C, const float* __restrict__ bias, int eOff)
{
    __shared__ float As[128 * 32], Bs[128 * 32];
    int z = blockIdx.z;
    int cnt = g_cnt[z + eOff];
    if ((int)blockIdx.y * 128 >= cnt) return;
    A += (long)z * BB * HH;
    B += (long)z * OUTD * HH;
    C += (long)z * BB * OUTD;
    int m0 = blockIdx.y * 128, n0 = blockIdx.x * 128;
    int tid = threadIdx.x, lane = tid & 31, wid = tid >> 5;
    int wm = wid >> 1, wn = wid & 1;
    float acc[2][8][4] = {};

    for (int kb = 0; kb < HH; kb += 32) {
#pragma unroll
        for (int i = 0; i < 4; i++) {
            int f = tid + i * 256;
            int r = f >> 3, c4 = (f & 7) * 4;
            int sc = c4 ^ ((r & 7) << 2);
            *(float4*)&As[r * 32 + sc] = *(const float4*)(A + (long)(m0 + r) * HH + kb + c4);
            *(float4*)&Bs[r * 32 + sc] = *(const float4*)(B + (long)(n0 + r) * HH + kb + c4);
        }
        __syncthreads();
#pragma unroll
        for (int ks = 0; ks < 4; ks++) {
            int k0 = ks * 8;
            unsigned af[2][4], bf[8][2];
#pragma unroll
            for (int mt = 0; mt < 2; mt++) {
                int r = wm * 32 + mt * 16 + (lane >> 2);
                int c = k0 + (lane & 3);
                int sw = (r & 7) << 2;
                int r8 = r + 8, sw8 = (r8 & 7) << 2;
                af[mt][0] = tf32r(As[r  * 32 + (c ^ sw)]);
                af[mt][1] = tf32r(As[r8 * 32 + (c ^ sw8)]);
                af[mt][2] = tf32r(As[r  * 32 + ((c + 4) ^ sw)]);
                af[mt][3] = tf32r(As[r8 * 32 + ((c + 4) ^ sw8)]);
            }
#pragma unroll
            for (int nt = 0; nt < 8; nt++) {
                int rn = wn * 64 + nt * 8 + (lane >> 2);
                int ck = k0 + (lane & 3);
                int sw = (rn & 7) << 2;
                bf[nt][0] = tf32r(Bs[rn * 32 + (ck ^ sw)]);
                bf[nt][1] = tf32r(Bs[rn * 32 + ((ck + 4) ^ sw)]);
            }
#pragma unroll
            for (int mt = 0; mt < 2; mt++)
#pragma unroll
                for (int nt = 0; nt < 8; nt++) {
                    asm volatile(
                        "mma.sync.aligned.m16n8k8.row.col.f32.tf32.tf32.f32 "
                        "{%0,%1,%2,%3}, {%4,%5,%6,%7}, {%8,%9}, {%0,%1,%2,%3};\n"
                        : "+f"(acc[mt][nt][0]), "+f"(acc[mt][nt][1]),
                          "+f"(acc[mt][nt][2]), "+f"(acc[mt][nt][3])
                        : "r"(af[mt][0]), "r"(af[mt][1]), "r"(af[mt][2]), "r"(af[mt][3]),
                          "r"(bf[nt][0]), "r"(bf[nt][1]));
                }
        }
        __syncthreads();
    }
#pragma unroll
    for (int mt = 0; mt < 2; mt++) {
        int r = m0 + wm * 32 + mt * 16 + (lane >> 2);
        int bi0 = (r < cnt)     ? g_idx[(z + eOff) * BB + r]     : -1;
        int bi1 = (r + 8 < cnt) ? g_idx[(z + eOff) * BB + r + 8] : -1;
#pragma unroll
        for (int nt = 0; nt < 8; nt++) {
            int c = n0 + wn * 64 + nt * 8 + (lane & 3) * 2;
            const float* bp = bias + (long)z * OUTD;
            float b0 = bp[c], b1v = bp[c + 1];
            if (bi0 >= 0)
                *(float2*)&C[(long)bi0 * OUTD + c] =
                    make_float2(acc[mt][nt][0] + b0, acc[mt][nt][1] + b1v);
            if (bi1 >= 0)
                *(float2*)&C[(long)bi1 * OUTD + c] =
                    make_float2(acc[mt][nt][2] + b0, acc[mt][nt][3] + b1v);
        }
    }
}

// ---------------- final combine ----------------
__global__ void combine_kernel(float* __restrict__ out) {
    int idx = blockIdx.x * blockDim.x + threadIdx.x;  // B*OUT
    int b = idx >> 9, o = idx & 511;
    float s = 0.f;
#pragma unroll
    for (int e = 0; e < NE; e++)
        s += g_w[b * NE + e] * g_eo[((long)e * BB + b) * OUTD + o];
    out[idx] = s;
}

// ---------------- launch ----------------
extern "C" void kernel_launch(void* const* d_in, const int* in_sizes, int n_in,
                              void* d_out, int out_size)
{
    const float* x    = (const float*)d_in[0];
    const float* Wg   = (const float*)d_in[1];
    const float* bg   = (const float*)d_in[2];
    const float* Wih  = (const float*)d_in[3];
    const float* Whh  = (const float*)d_in[4];
    const float* bih  = (const float*)d_in[5];
    const float* bhh  = (const float*)d_in[6];
    const float* fcW  = (const float*)d_in[7];
    const float* fcb  = (const float*)d_in[8];
    const float* W1   = (const float*)d_in[9];
    const float* b1   = (const float*)d_in[10];
    const float* W2   = (const float*)d_in[11];
    const float* b2   = (const float*)d_in[12];
    float* out = (float*)d_out;

    const int LG_SMEM = 1024 + 128 * 132 * 4;   // 68608 (>= 1024 + 2*32768 = 66560)
    cudaFuncSetAttribute(lstm_gemm, cudaFuncAttributeMaxDynamicSharedMemorySize, LG_SMEM);

    __half *xcP, *hb0;
    float *wp, *eop, *h1buf, *hfP;
    cudaGetSymbolAddress((void**)&xcP,   g_xpadC);
    cudaGetSymbolAddress((void**)&hb0,   g_hblk);
    cudaGetSymbolAddress((void**)&wp,    g_w);
    cudaGetSymbolAddress((void**)&eop,   g_eo);
    cudaGetSymbolAddress((void**)&h1buf, g_h1);
    cudaGetSymbolAddress((void**)&hfP,   g_hf);
    __half* hb1 = hb0 + (size_t)NER * 16 * BB * 32;
    __half* hbuf[2] = { hb0, hb1 };

    gate_kernel<<<BB, 256>>>(x, Wg, bg, wp);
    int nPrep = (int)(((long)NER * G4H * 544 + 255) / 256);
    prep_compact<<<nPrep + NE, 256>>>(Whh, Wih, bih, bhh);
    prep_xc<<<(int)(((long)TT * NER * BB * 32 + 255) / 256), 256>>>(x);

    for (int t = 0; t < TT; t++) {
        lstm_gemm<<<dim3(16, 16, NER), 256, LG_SMEM>>>(
            hbuf[t & 1], hbuf[(t + 1) & 1],
            (t == TT - 1) ? hfP : (float*)0,
            xcP + (size_t)t * NER * BB * 32, t == 0 ? 16 : 0);
    }

    // rec_out: compact hLast -> scatter into dense g_eo[0..3]
    fc_gemm_scatter<<<dim3(4, 16, NER), 256>>>(hfP, fcW, eop, fcb, 0);

    // h1 = relu(x_gathered @ W1^T + b1), compact rows per simple expert
    h1_gemm_gather<<<dim3(4, 16, NER), 256>>>(x, W1, h1buf, b1);

    // simp = h1_compact @ W2^T + b2 -> scatter into dense g_eo[4..7]
    fc_gemm_scatter<<<dim3(4, 16, NER), 256>>>(
        h1buf, W2, eop + (size_t)NER * BB * OUTD, b2, 4);

    combine_kernel<<<(BB * OUTD) / 256, 256>>>(out);
}